// round 11
// baseline (speedup 1.0000x reference)
#include <cuda_runtime.h>
#include <cstdint>

// ---------------------------------------------------------------------------
// TemporalAttentionPooling (GB300 / sm_103a) — Round 8
//   scores = tanh(x @ W1 + b1) @ W2 + b2   (MLP 128->32->1)
//   per-segment softmax (max-free: bounded scores) -> pooled = sum e x / sum e
//
// R8 vs R7 (294.8 us, ~50% L1 busy -> latency-bound at 8 warps/SM):
//   - 1 block x 384 threads per SM (12 warps, +50% occupancy), W1 table
//     shared once per SM, 208 KB dynamic smem
//   - SINGLE launch: normalize/zero/pids phase fused behind a grid-wide
//     arrive/spin barrier (152 blocks = 1/SM, co-resident by construction)
//   - hot loop identical to R7 (flat streaming, cp.async double buffer,
//     16-row units, atomicAdd segment flush)
// ---------------------------------------------------------------------------

#define RPG    16
#define PMAX   16384
#define NWARP  12
#define NTHR   (NWARP * 32)
#define GRID   152

__device__ float g_acc[PMAX * 128];   // unnormalized pooled sums (self-zeroing)
__device__ float g_S[PMAX];           // exp-sum denominators    (self-zeroing)
__device__ int   g_arrive;            // grid barrier (self-resetting)
__device__ int   g_depart;

static __device__ __forceinline__ unsigned long long f2pack(float lo, float hi) {
    unsigned long long r;
    asm("mov.b64 %0, {%1, %2};" : "=l"(r) : "f"(lo), "f"(hi));
    return r;
}
static __device__ __forceinline__ void f2unpack(unsigned long long v, float& lo, float& hi) {
    asm("mov.b64 {%0, %1}, %2;" : "=f"(lo), "=f"(hi) : "l"(v));
}
static __device__ __forceinline__ unsigned long long ffma2(unsigned long long a,
                                                           unsigned long long b,
                                                           unsigned long long c) {
    unsigned long long d;
    asm("fma.rn.f32x2 %0, %1, %2, %3;" : "=l"(d) : "l"(a), "l"(b), "l"(c));
    return d;
}
static __device__ __forceinline__ void cp_async16(uint32_t dst, const void* src, int pred) {
    asm volatile(
        "{ .reg .pred p;\n"
        "  setp.ne.u32 p, %2, 0;\n"
        "  @p cp.async.cg.shared.global [%0], [%1], 16; }\n"
        :: "r"(dst), "l"(src), "r"(pred));
}
#define CP_COMMIT() asm volatile("cp.async.commit_group;" ::: "memory")
#define CP_WAIT1()  asm volatile("cp.async.wait_group 1;" ::: "memory")

// dynamic smem: [0,16K) w1t k-paired W1; [16K, 16K+12*16K) per-warp stages
#define SMEM_BYTES (16384 + NWARP * 16384)

__global__ void __launch_bounds__(NTHR, 1)
k_main(const float* __restrict__ x,
       const int*   __restrict__ pid,
       const float* __restrict__ W1,   // (128, 32) row-major
       const float* __restrict__ b1,   // (32,)
       const float* __restrict__ W2,   // (32,)
       const float* __restrict__ b2,   // (1,)
       float* __restrict__ out,        // (P,128) then pids (P,) if present
       int n, int nUnits, int P, int has_pids) {
    extern __shared__ __align__(16) char smem_raw[];
    ulonglong2* w1t   = reinterpret_cast<ulonglong2*>(smem_raw);
    float*      stage = reinterpret_cast<float*>(smem_raw + 16384);

    const int tid  = threadIdx.x;
    const int wid  = tid >> 5;
    const int lane = tid & 31;
    const int j2   = lane & 7;      // hidden group: j = 4*j2..4*j2+3
    const int r2   = lane >> 3;     // row subgroup base: rows r2+{0,4,8,12}

    // ---- k-paired W1 table (packing verified R4/R6/R7) ---------------------
    {
        float* w1f = reinterpret_cast<float*>(w1t);
        for (int q4 = tid; q4 < 4096; q4 += NTHR) {
            int q    = q4 >> 2, slot = q4 & 3;
            int kp   = q >> 4, rem = q & 15;
            int part = rem >> 3, jq = rem & 7;
            int j    = 4 * jq + 2 * part + (slot >> 1);
            int krow = 2 * kp + (slot & 1);
            w1f[q4] = W1[krow * 32 + j];
        }
    }
    const float4 b1q = reinterpret_cast<const float4*>(b1)[j2];
    const float4 w2q = reinterpret_cast<const float4*>(W2)[j2];
    const float  b2s = b2[0];
    __syncthreads();

    const uint32_t st_sh =
        (uint32_t)__cvta_generic_to_shared(stage) + (uint32_t)wid * 16384u;
    float* const stw = stage + wid * 4096;   // this warp's 2 bufs x 2048 floats

    // ---- contiguous unit range for this warp -------------------------------
    const int nW = GRID * NWARP;
    const int gw = blockIdx.x * NWARP + wid;
    const long long u0 = ((long long)gw * nUnits) / nW;
    const long long u1 = ((long long)(gw + 1) * nUnits) / nW;

    unsigned long long pa0 = 0ull, pa1 = 0ull;  // running pooled dims 4l..4l+3
    float Ssum   = 0.0f;
    int   curPid = -1;

    int ibuf = 0;
    int pidNext = -2;
    if (u0 < u1) {                    // prologue: issue unit u0 into buf 0
        const int   br  = (int)(u0 * RPG);
        const float* sp = x + (size_t)br * 128 + lane * 4;
#pragma unroll
        for (int r = 0; r < RPG; r++)
            cp_async16(st_sh + (uint32_t)(r * 512 + ((lane ^ r) << 4)),
                       sp + (size_t)r * 128, (br + r) < n);
        if (lane < 16 && (br + lane) < n) pidNext = pid[br + lane];
    }
    CP_COMMIT();

    for (long long uu = u0; uu < u1; ++uu) {
        const int pidCur = pidNext;
        const int nb = ibuf ^ 1;
        if (uu + 1 < u1) {            // issue next unit (linear address)
            const int   br  = (int)((uu + 1) * RPG);
            const float* sp = x + (size_t)br * 128 + lane * 4;
            const uint32_t xbA = st_sh + (uint32_t)nb * 8192u;
#pragma unroll
            for (int r = 0; r < RPG; r++)
                cp_async16(xbA + (uint32_t)(r * 512 + ((lane ^ r) << 4)),
                           sp + (size_t)r * 128, (br + r) < n);
            pidNext = -2;
            if (lane < 16 && (br + lane) < n) pidNext = pid[br + lane];
        }
        CP_COMMIT();
        CP_WAIT1();                   // current unit complete

        const int baseRow   = (int)(uu * RPG);
        const int rowsValid = min(RPG, n - baseRow);
        const float* xb = stw + ibuf * 2048;

        // ---- MLP: 16 rows, acc[4 row-subgroups][4 hidden] ------------------
        unsigned long long acc[4][4];
#pragma unroll
        for (int rr = 0; rr < 4; rr++)
#pragma unroll
            for (int jj = 0; jj < 4; jj++) acc[rr][jj] = 0ull;

#pragma unroll 8
        for (int t = 0; t < 32; t++) {
            ulonglong2 wA0 = w1t[32 * t + j2];
            ulonglong2 wA1 = w1t[32 * t + 8 + j2];
            ulonglong2 wB0 = w1t[32 * t + 16 + j2];
            ulonglong2 wB1 = w1t[32 * t + 24 + j2];
#pragma unroll
            for (int rr = 0; rr < 4; rr++) {
                const int row = r2 + 4 * rr;
                ulonglong2 xq = *reinterpret_cast<const ulonglong2*>(
                                    xb + row * 128 + ((t ^ row) << 2));
                acc[rr][0] = ffma2(xq.x, wA0.x, acc[rr][0]);
                acc[rr][1] = ffma2(xq.x, wA0.y, acc[rr][1]);
                acc[rr][2] = ffma2(xq.x, wA1.x, acc[rr][2]);
                acc[rr][3] = ffma2(xq.x, wA1.y, acc[rr][3]);
                acc[rr][0] = ffma2(xq.y, wB0.x, acc[rr][0]);
                acc[rr][1] = ffma2(xq.y, wB0.y, acc[rr][1]);
                acc[rr][2] = ffma2(xq.y, wB1.x, acc[rr][2]);
                acc[rr][3] = ffma2(xq.y, wB1.y, acc[rr][3]);
            }
        }

        // ---- epilogue: tanh + W2 dot + j2-octet reduce -> e per row --------
        float ev[4];
#pragma unroll
        for (int rr = 0; rr < 4; rr++) {
            float s = 0.0f;
#pragma unroll
            for (int jj = 0; jj < 4; jj++) {
                float lo, hi;
                f2unpack(acc[rr][jj], lo, hi);
                float h = lo + hi + reinterpret_cast<const float*>(&b1q)[jj];
                s += tanhf(h) * reinterpret_cast<const float*>(&w2q)[jj];
            }
            s += __shfl_xor_sync(0xffffffffu, s, 1);
            s += __shfl_xor_sync(0xffffffffu, s, 2);
            s += __shfl_xor_sync(0xffffffffu, s, 4);
            ev[rr] = expf(s + b2s);     // bounded scores: no overflow
        }

        // ---- pooling with inline segment flush (rows in order) -------------
#pragma unroll
        for (int r = 0; r < RPG; r++) {
            if (r < rowsValid) {
                int pr = __shfl_sync(0xffffffffu, pidCur, r);
                if (pr != curPid) {
                    if (curPid >= 0) {
                        float4 pv;
                        f2unpack(pa0, pv.x, pv.y);
                        f2unpack(pa1, pv.z, pv.w);
                        float* dst = g_acc + (size_t)curPid * 128 + 4 * lane;
                        atomicAdd(dst + 0, pv.x);
                        atomicAdd(dst + 1, pv.y);
                        atomicAdd(dst + 2, pv.z);
                        atomicAdd(dst + 3, pv.w);
                        if (lane == 0) atomicAdd(&g_S[curPid], Ssum);
                    }
                    pa0 = 0ull; pa1 = 0ull; Ssum = 0.0f;
                    curPid = pr;
                }
                float evsel = (r >> 2) == 0 ? ev[0] : (r >> 2) == 1 ? ev[1]
                             : (r >> 2) == 2 ? ev[2] : ev[3];
                float ew = __shfl_sync(0xffffffffu, evsel, (r & 3) * 8);
                Ssum += ew;
                ulonglong2 xq = *reinterpret_cast<const ulonglong2*>(
                                    xb + r * 128 + ((lane ^ r) << 2));
                unsigned long long eq = f2pack(ew, ew);
                pa0 = ffma2(xq.x, eq, pa0);
                pa1 = ffma2(xq.y, eq, pa1);
            }
        }
        ibuf = nb;
    }

    // final flush
    if (curPid >= 0) {
        float4 pv;
        f2unpack(pa0, pv.x, pv.y);
        f2unpack(pa1, pv.z, pv.w);
        float* dst = g_acc + (size_t)curPid * 128 + 4 * lane;
        atomicAdd(dst + 0, pv.x);
        atomicAdd(dst + 1, pv.y);
        atomicAdd(dst + 2, pv.z);
        atomicAdd(dst + 3, pv.w);
        if (lane == 0) atomicAdd(&g_S[curPid], Ssum);
    }

    // ---- grid-wide barrier (152 blocks = 1/SM, co-resident) ----------------
    __threadfence();
    __syncthreads();
    if (tid == 0) {
        atomicAdd(&g_arrive, 1);
        while (*(volatile int*)&g_arrive < gridDim.x) { __nanosleep(64); }
    }
    __syncthreads();
    __threadfence();

    // ---- normalize phase: block owns p in [p0, p1) -------------------------
    {
        const int p0 = (int)(((long long)blockIdx.x * P) / GRID);
        const int p1 = (int)(((long long)(blockIdx.x + 1) * P) / GRID);
        for (int i = p0 * 128 + tid; i < p1 * 128; i += NTHR) {
            int p = i >> 7;
            float S = g_S[p];
            out[i] = g_acc[i] / ((S > 0.0f) ? S : 1.0f);
            g_acc[i] = 0.0f;                   // re-arm for next graph replay
        }
        if (has_pids) {
            float* outpids = out + (size_t)P * 128;
            for (int p = p0 + tid; p < p1; p += NTHR) outpids[p] = (float)p;
        }
        __syncthreads();                        // all reads of g_S done
        for (int p = p0 + tid; p < p1; p += NTHR) g_S[p] = 0.0f;
    }

    // ---- barrier self-reset for next replay --------------------------------
    __syncthreads();
    if (tid == 0) {
        int d = atomicAdd(&g_depart, 1);
        if (d == gridDim.x - 1) {               // last block out resets
            g_arrive = 0;
            g_depart = 0;
            __threadfence();
        }
    }
}

// ---------------------------------------------------------------------------
extern "C" void kernel_launch(void* const* d_in, const int* in_sizes, int n_in,
                              void* d_out, int out_size) {
    const float* x   = (const float*)d_in[0];
    const int*   pid = (const int*)  d_in[1];
    const float* W1  = (const float*)d_in[2];
    const float* b1  = (const float*)d_in[3];
    const float* W2  = (const float*)d_in[4];
    const float* b2  = (const float*)d_in[5];
    float* out = (float*)d_out;

    const int n = in_sizes[1];       // N rows
    const int D = 128;

    int P;
    int has_pids;
    if (out_size % (D + 1) == 0) { P = out_size / (D + 1); has_pids = 1; }
    else                         { P = out_size / D;       has_pids = 0; }
    if (P > PMAX) P = PMAX;

    static bool attr_set = false;
    if (!attr_set) {
        cudaFuncSetAttribute(k_main,
                             cudaFuncAttributeMaxDynamicSharedMemorySize,
                             SMEM_BYTES);
        attr_set = true;
    }

    const int nUnits = (n + RPG - 1) / RPG;
    k_main<<<GRID, NTHR, SMEM_BYTES>>>(x, pid, W1, b1, W2, b2, out,
                                       n, nUnits, P, has_pids);
}

// round 12
// speedup vs baseline: 1.3095x; 1.3095x over previous
#include <cuda_runtime.h>
#include <cstdint>

// ---------------------------------------------------------------------------
// TemporalAttentionPooling (GB300 / sm_103a) — Round 11
//   scores = tanh(x @ W1 + b1) @ W2 + b2   (MLP 128->32->1)
//   per-segment softmax (max-free: bounded scores) -> pooled = sum e x / sum e
//
// R11 vs R8 (306.7 us; issue 48%, alu 23.5%, L1 63% — overhead-bound):
//   - tanh/exp via __expf + __fdividef (6 instr vs ~20; rel err ~1e-6)
//   - staged rows at stride 132 floats (528 B): bank-skew replaces XOR
//     swizzle -> zero LOP/SHF on LDS addresses
//   - single-segment fast path (sorted pids): ~77% of 16-row units skip
//     all per-row pid logic
//   - hoisted full-unit bounds check
//   skeleton unchanged: flat streaming, cp.async double buffer, atomicAdd
//   segment flush, fused normalize behind grid-wide spin barrier
// ---------------------------------------------------------------------------

#define RPG     16
#define PMAX    16384
#define NWARP   12
#define NTHR    (NWARP * 32)
#define GRID    152
#define RSTRIDE 132                  // floats per staged row (528 B)
#define BUFF    (RPG * RSTRIDE)      // 2112 floats per buffer
#define WSTRIDE (2 * BUFF)           // 4224 floats per warp (2 buffers)

__device__ float g_acc[PMAX * 128];  // unnormalized pooled sums (self-zeroing)
__device__ float g_S[PMAX];          // exp-sum denominators    (self-zeroing)
__device__ int   g_arrive;           // grid barrier (self-resetting)
__device__ int   g_depart;

static __device__ __forceinline__ unsigned long long f2pack(float lo, float hi) {
    unsigned long long r;
    asm("mov.b64 %0, {%1, %2};" : "=l"(r) : "f"(lo), "f"(hi));
    return r;
}
static __device__ __forceinline__ void f2unpack(unsigned long long v, float& lo, float& hi) {
    asm("mov.b64 {%0, %1}, %2;" : "=f"(lo), "=f"(hi) : "l"(v));
}
static __device__ __forceinline__ unsigned long long ffma2(unsigned long long a,
                                                           unsigned long long b,
                                                           unsigned long long c) {
    unsigned long long d;
    asm("fma.rn.f32x2 %0, %1, %2, %3;" : "=l"(d) : "l"(a), "l"(b), "l"(c));
    return d;
}
static __device__ __forceinline__ void cp_async16(uint32_t dst, const void* src, int pred) {
    asm volatile(
        "{ .reg .pred p;\n"
        "  setp.ne.u32 p, %2, 0;\n"
        "  @p cp.async.cg.shared.global [%0], [%1], 16; }\n"
        :: "r"(dst), "l"(src), "r"(pred));
}
#define CP_COMMIT() asm volatile("cp.async.commit_group;" ::: "memory")
#define CP_WAIT1()  asm volatile("cp.async.wait_group 1;" ::: "memory")

// cheap accurate tanh: (e^{2h}-1)/(e^{2h}+1); |h|<~20 so no overflow; err ~1e-6
static __device__ __forceinline__ float tanh_fast(float h) {
    float t = __expf(2.0f * h);
    return __fdividef(t - 1.0f, t + 1.0f);
}

static __device__ __forceinline__ void flush_seg(int pidv,
                                                 unsigned long long& pa0,
                                                 unsigned long long& pa1,
                                                 float& Ssum, int lane) {
    if (pidv >= 0) {
        float a, b, c, d;
        f2unpack(pa0, a, b);
        f2unpack(pa1, c, d);
        float* dst = g_acc + (size_t)pidv * 128 + 4 * lane;
        atomicAdd(dst + 0, a);
        atomicAdd(dst + 1, b);
        atomicAdd(dst + 2, c);
        atomicAdd(dst + 3, d);
        if (lane == 0) atomicAdd(&g_S[pidv], Ssum);
    }
    pa0 = 0ull; pa1 = 0ull; Ssum = 0.0f;
}

// dynamic smem: [0,16K) w1t; [16K, 16K + NWARP*WSTRIDE*4) per-warp stages
#define SMEM_BYTES (16384 + NWARP * WSTRIDE * 4)

__global__ void __launch_bounds__(NTHR, 1)
k_main(const float* __restrict__ x,
       const int*   __restrict__ pid,
       const float* __restrict__ W1,   // (128, 32) row-major
       const float* __restrict__ b1,   // (32,)
       const float* __restrict__ W2,   // (32,)
       const float* __restrict__ b2,   // (1,)
       float* __restrict__ out,        // (P,128) then pids (P,) if present
       int n, int nUnits, int P, int has_pids) {
    extern __shared__ __align__(16) char smem_raw[];
    ulonglong2* w1t   = reinterpret_cast<ulonglong2*>(smem_raw);
    float*      stage = reinterpret_cast<float*>(smem_raw + 16384);

    const int tid  = threadIdx.x;
    const int wid  = tid >> 5;
    const int lane = tid & 31;
    const int j2   = lane & 7;      // hidden group: j = 4*j2..4*j2+3
    const int r2   = lane >> 3;     // row subgroup base: rows r2+{0,4,8,12}

    // ---- k-paired W1 table (packing verified R4..R8) -----------------------
    {
        float* w1f = reinterpret_cast<float*>(w1t);
        for (int q4 = tid; q4 < 4096; q4 += NTHR) {
            int q    = q4 >> 2, slot = q4 & 3;
            int kp   = q >> 4, rem = q & 15;
            int part = rem >> 3, jq = rem & 7;
            int j    = 4 * jq + 2 * part + (slot >> 1);
            int krow = 2 * kp + (slot & 1);
            w1f[q4] = W1[krow * 32 + j];
        }
    }
    const float4 b1q = reinterpret_cast<const float4*>(b1)[j2];
    const float4 w2q = reinterpret_cast<const float4*>(W2)[j2];
    const float  b2s = b2[0];
    __syncthreads();

    const uint32_t st_sh =
        (uint32_t)__cvta_generic_to_shared(stage) + (uint32_t)(wid * WSTRIDE * 4);
    float* const stw = stage + wid * WSTRIDE;

    // ---- contiguous unit range for this warp -------------------------------
    const int nW = GRID * NWARP;
    const int gw = blockIdx.x * NWARP + wid;
    const long long u0 = ((long long)gw * nUnits) / nW;
    const long long u1 = ((long long)(gw + 1) * nUnits) / nW;

    unsigned long long pa0 = 0ull, pa1 = 0ull;  // running pooled dims 4l..4l+3
    float Ssum   = 0.0f;
    int   curPid = -1;

    int ibuf = 0;
    int pidNext = -2;
    if (u0 < u1) {                    // prologue: issue unit u0 into buf 0
        const int   br  = (int)(u0 * RPG);
        const float* sp = x + (size_t)br * 128 + lane * 4;
        if (br + RPG <= n) {
#pragma unroll
            for (int r = 0; r < RPG; r++)
                cp_async16(st_sh + (uint32_t)(r * 528 + (lane << 4)),
                           sp + (size_t)r * 128, 1);
        } else {
#pragma unroll
            for (int r = 0; r < RPG; r++)
                cp_async16(st_sh + (uint32_t)(r * 528 + (lane << 4)),
                           sp + (size_t)r * 128, (br + r) < n);
        }
        if (lane < RPG && (br + lane) < n) pidNext = pid[br + lane];
    }
    CP_COMMIT();

    for (long long uu = u0; uu < u1; ++uu) {
        const int pidCur = pidNext;
        const int nb = ibuf ^ 1;
        if (uu + 1 < u1) {            // issue next unit (linear addresses)
            const int   br  = (int)((uu + 1) * RPG);
            const float* sp = x + (size_t)br * 128 + lane * 4;
            const uint32_t xbA = st_sh + (uint32_t)(nb * BUFF * 4);
            if (br + RPG <= n) {
#pragma unroll
                for (int r = 0; r < RPG; r++)
                    cp_async16(xbA + (uint32_t)(r * 528 + (lane << 4)),
                               sp + (size_t)r * 128, 1);
            } else {
#pragma unroll
                for (int r = 0; r < RPG; r++)
                    cp_async16(xbA + (uint32_t)(r * 528 + (lane << 4)),
                               sp + (size_t)r * 128, (br + r) < n);
            }
            pidNext = -2;
            if (lane < RPG && (br + lane) < n) pidNext = pid[br + lane];
        }
        CP_COMMIT();
        CP_WAIT1();                   // current unit complete

        const int baseRow   = (int)(uu * RPG);
        const int rowsValid = min(RPG, n - baseRow);
        const float* xb = stw + ibuf * BUFF;

        // ---- MLP: 16 rows, acc[4 row-subgroups][4 hidden] ------------------
        unsigned long long acc[4][4];
#pragma unroll
        for (int rr = 0; rr < 4; rr++)
#pragma unroll
            for (int jj = 0; jj < 4; jj++) acc[rr][jj] = 0ull;

#pragma unroll 8
        for (int t = 0; t < 32; t++) {
            ulonglong2 wA0 = w1t[32 * t + j2];
            ulonglong2 wA1 = w1t[32 * t + 8 + j2];
            ulonglong2 wB0 = w1t[32 * t + 16 + j2];
            ulonglong2 wB1 = w1t[32 * t + 24 + j2];
#pragma unroll
            for (int rr = 0; rr < 4; rr++) {
                const int row = r2 + 4 * rr;
                ulonglong2 xq = *reinterpret_cast<const ulonglong2*>(
                                    xb + row * RSTRIDE + t * 4);
                acc[rr][0] = ffma2(xq.x, wA0.x, acc[rr][0]);
                acc[rr][1] = ffma2(xq.x, wA0.y, acc[rr][1]);
                acc[rr][2] = ffma2(xq.x, wA1.x, acc[rr][2]);
                acc[rr][3] = ffma2(xq.x, wA1.y, acc[rr][3]);
                acc[rr][0] = ffma2(xq.y, wB0.x, acc[rr][0]);
                acc[rr][1] = ffma2(xq.y, wB0.y, acc[rr][1]);
                acc[rr][2] = ffma2(xq.y, wB1.x, acc[rr][2]);
                acc[rr][3] = ffma2(xq.y, wB1.y, acc[rr][3]);
            }
        }

        // ---- epilogue: tanh + W2 dot + j2-octet reduce -> e per row --------
        float ev[4];
#pragma unroll
        for (int rr = 0; rr < 4; rr++) {
            float s = 0.0f;
#pragma unroll
            for (int jj = 0; jj < 4; jj++) {
                float lo, hi;
                f2unpack(acc[rr][jj], lo, hi);
                float h = lo + hi + reinterpret_cast<const float*>(&b1q)[jj];
                s += tanh_fast(h) * reinterpret_cast<const float*>(&w2q)[jj];
            }
            s += __shfl_xor_sync(0xffffffffu, s, 1);
            s += __shfl_xor_sync(0xffffffffu, s, 2);
            s += __shfl_xor_sync(0xffffffffu, s, 4);
            ev[rr] = __expf(s + b2s);   // bounded scores: no overflow
        }

        // ---- pooling -------------------------------------------------------
        const int pidFirst = __shfl_sync(0xffffffffu, pidCur, 0);
        const int pidLast  = __shfl_sync(0xffffffffu, pidCur, RPG - 1);
        if (pidFirst == pidLast && rowsValid == RPG) {
            // fast path: whole unit in one segment (sorted pids)
            if (pidFirst != curPid) {
                flush_seg(curPid, pa0, pa1, Ssum, lane);
                curPid = pidFirst;
            }
            float s4 = (ev[0] + ev[1]) + (ev[2] + ev[3]);  // 4 rows per lane
            s4 += __shfl_xor_sync(0xffffffffu, s4, 8);
            s4 += __shfl_xor_sync(0xffffffffu, s4, 16);
            Ssum += s4;
#pragma unroll
            for (int r = 0; r < RPG; r++) {
                float ew = __shfl_sync(0xffffffffu, ev[r >> 2], (r & 3) * 8);
                ulonglong2 xq = *reinterpret_cast<const ulonglong2*>(
                                    xb + r * RSTRIDE + lane * 4);
                unsigned long long eq = f2pack(ew, ew);
                pa0 = ffma2(xq.x, eq, pa0);
                pa1 = ffma2(xq.y, eq, pa1);
            }
        } else {
            // slow path: per-row pid tracking
#pragma unroll
            for (int r = 0; r < RPG; r++) {
                if (r < rowsValid) {
                    int pr = __shfl_sync(0xffffffffu, pidCur, r);
                    if (pr != curPid) {
                        flush_seg(curPid, pa0, pa1, Ssum, lane);
                        curPid = pr;
                    }
                    float ew = __shfl_sync(0xffffffffu, ev[r >> 2], (r & 3) * 8);
                    Ssum += ew;
                    ulonglong2 xq = *reinterpret_cast<const ulonglong2*>(
                                        xb + r * RSTRIDE + lane * 4);
                    unsigned long long eq = f2pack(ew, ew);
                    pa0 = ffma2(xq.x, eq, pa0);
                    pa1 = ffma2(xq.y, eq, pa1);
                }
            }
        }
        ibuf = nb;
    }

    // final flush
    flush_seg(curPid, pa0, pa1, Ssum, lane);

    // ---- grid-wide barrier (152 blocks = 1/SM, co-resident) ----------------
    __threadfence();
    __syncthreads();
    if (tid == 0) {
        atomicAdd(&g_arrive, 1);
        while (*(volatile int*)&g_arrive < gridDim.x) { __nanosleep(64); }
    }
    __syncthreads();
    __threadfence();

    // ---- normalize phase: block owns p in [p0, p1) -------------------------
    {
        const int p0 = (int)(((long long)blockIdx.x * P) / GRID);
        const int p1 = (int)(((long long)(blockIdx.x + 1) * P) / GRID);
        for (int i = p0 * 128 + tid; i < p1 * 128; i += NTHR) {
            int p = i >> 7;
            float S = g_S[p];
            out[i] = g_acc[i] / ((S > 0.0f) ? S : 1.0f);
            g_acc[i] = 0.0f;                   // re-arm for next graph replay
        }
        if (has_pids) {
            float* outpids = out + (size_t)P * 128;
            for (int p = p0 + tid; p < p1; p += NTHR) outpids[p] = (float)p;
        }
        __syncthreads();                        // all reads of g_S done
        for (int p = p0 + tid; p < p1; p += NTHR) g_S[p] = 0.0f;
    }

    // ---- barrier self-reset for next replay --------------------------------
    __syncthreads();
    if (tid == 0) {
        int d = atomicAdd(&g_depart, 1);
        if (d == gridDim.x - 1) {
            g_arrive = 0;
            g_depart = 0;
            __threadfence();
        }
    }
}

// ---------------------------------------------------------------------------
extern "C" void kernel_launch(void* const* d_in, const int* in_sizes, int n_in,
                              void* d_out, int out_size) {
    const float* x   = (const float*)d_in[0];
    const int*   pid = (const int*)  d_in[1];
    const float* W1  = (const float*)d_in[2];
    const float* b1  = (const float*)d_in[3];
    const float* W2  = (const float*)d_in[4];
    const float* b2  = (const float*)d_in[5];
    float* out = (float*)d_out;

    const int n = in_sizes[1];       // N rows
    const int D = 128;

    int P;
    int has_pids;
    if (out_size % (D + 1) == 0) { P = out_size / (D + 1); has_pids = 1; }
    else                         { P = out_size / D;       has_pids = 0; }
    if (P > PMAX) P = PMAX;

    static bool attr_set = false;
    if (!attr_set) {
        cudaFuncSetAttribute(k_main,
                             cudaFuncAttributeMaxDynamicSharedMemorySize,
                             SMEM_BYTES);
        attr_set = true;
    }

    const int nUnits = (n + RPG - 1) / RPG;
    k_main<<<GRID, NTHR, SMEM_BYTES>>>(x, pid, W1, b1, W2, b2, out,
                                       n, nUnits, P, has_pids);
}